// round 1
// baseline (speedup 1.0000x reference)
#include <cuda_runtime.h>
#include <cuda_bf16.h>

#define NN 64
#define PAD 65          // smem row pad: transpose reads become ~2-way conflicts
#define ROWLEN 4096     // 64*64
#define THREADS 256

__global__ __launch_bounds__(THREADS)
void sym_equiv_kernel(const float* __restrict__ X,
                      const float* __restrict__ w,
                      float* __restrict__ out)
{
    __shared__ float Xs[NN * PAD];     // 16,640 B
    __shared__ float R1[NN], R2[NN];
    __shared__ float Avec[NN], Cvec[NN], Evec[NN];
    __shared__ float sT, sD;
    __shared__ float ws[16];

    const int t = threadIdx.x;
    const int b = blockIdx.x;
    const float* __restrict__ xrow = X + (size_t)b * ROWLEN;

    if (t < 15) ws[t] = w[t];

    // ---- Phase 1: load row (coalesced float4), stage to padded smem,
    //      and accumulate per-thread partial of its 16 contiguous elements.
    const int j1 = t >> 2;             // row within 64x64 tile
    const int c0 = (t & 3) << 4;       // 16-col chunk start
    const float* g = xrow + j1 * NN + c0;
    float4 v0 = *(const float4*)(g + 0);
    float4 v1 = *(const float4*)(g + 4);
    float4 v2 = *(const float4*)(g + 8);
    float4 v3 = *(const float4*)(g + 12);

    float* srow = Xs + j1 * PAD + c0;
    srow[0]  = v0.x; srow[1]  = v0.y; srow[2]  = v0.z; srow[3]  = v0.w;
    srow[4]  = v1.x; srow[5]  = v1.y; srow[6]  = v1.z; srow[7]  = v1.w;
    srow[8]  = v2.x; srow[9]  = v2.y; srow[10] = v2.z; srow[11] = v2.w;
    srow[12] = v3.x; srow[13] = v3.y; srow[14] = v3.z; srow[15] = v3.w;

    float part = (v0.x + v0.y + v0.z + v0.w)
               + (v1.x + v1.y + v1.z + v1.w)
               + (v2.x + v2.y + v2.z + v2.w)
               + (v3.x + v3.y + v3.z + v3.w);
    // combine 4 lanes sharing one row -> R1[j1]
    part += __shfl_down_sync(0xffffffffu, part, 2, 4);
    part += __shfl_down_sync(0xffffffffu, part, 1, 4);
    if ((t & 3) == 0) R1[j1] = part;

    __syncthreads();

    // ---- Phase 2: column sums R2, plus scalars T and D.
    if (t < 64) {
        float s = 0.f;
        #pragma unroll
        for (int r = 0; r < NN; ++r) s += Xs[r * PAD + t];
        R2[t] = s;
    } else if (t < 96) {               // one warp: T = sum(R1)
        int l = t - 64;
        float s = R1[l] + R1[l + 32];
        #pragma unroll
        for (int o = 16; o > 0; o >>= 1) s += __shfl_xor_sync(0xffffffffu, s, o);
        if (l == 0) sT = s;
    } else if (t < 128) {              // one warp: D = trace
        int l = t - 96;
        float s = Xs[l * (PAD + 1)] + Xs[(l + 32) * (PAD + 1)];
        #pragma unroll
        for (int o = 16; o > 0; o >>= 1) s += __shfl_xor_sync(0xffffffffu, s, o);
        if (l == 0) sD = s;
    }

    __syncthreads();

    // ---- Phase 3: fold weights into per-index vectors.
    // Weight -> partition map (order of _set_partitions([0,1,2,3])):
    //  w0 {0123}     -> eq * Xd[i1]
    //  w1 {0}{123}   -> Xd[i2]
    //  w2 {01}{23}   -> eq * D
    //  w3 {023}{1}   -> Xd[i1]
    //  w4 {0}{1}{23} -> D
    //  w5 {012}{3}   -> eq * R1[i1]
    //  w6 {03}{12}   -> X[i2,i1]
    //  w7 {0}{12}{3} -> R1[i2]
    //  w8 {02}{13}   -> X[i1,i2]
    //  w9 {013}{2}   -> eq * R2[i1]
    //  w10 {0}{2}{13}-> R2[i2]
    //  w11 {01}{2}{3}-> eq * T
    //  w12 {02}{1}{3}-> R1[i1]
    //  w13 {03}{1}{2}-> R2[i1]
    //  w14 singletons-> T
    if (t < 64) {
        float r1 = R1[t], r2 = R2[t], xd = Xs[t * (PAD + 1)];
        Avec[t] = ws[12] * r1 + ws[13] * r2 + ws[3] * xd;              // i1 terms
        Cvec[t] = ws[7]  * r1 + ws[10] * r2 + ws[1] * xd;              // i2 terms
        Evec[t] = ws[5]  * r1 + ws[9]  * r2 + ws[0] * xd
                + ws[11] * sT + ws[2] * sD;                            // eq terms
    }

    __syncthreads();

    // ---- Phase 4: emit 16 outputs per thread, float4-coalesced.
    const float base = ws[14] * sT + ws[4] * sD;
    const float w8v = ws[8], w6v = ws[6];
    const int i1 = t >> 2;
    const int ib = (t & 3) << 4;
    const float K0 = base + Avec[i1];

    float* orow = out + (size_t)b * ROWLEN + i1 * NN + ib;
    const float* xr = Xs + i1 * PAD;   // direct row
    float res[16];
    #pragma unroll
    for (int j = 0; j < 16; ++j) {
        int i2 = ib + j;
        float val = K0 + Cvec[i2]
                  + w8v * xr[i2]
                  + w6v * Xs[i2 * PAD + i1];
        if (i2 == i1) val += Evec[i1];
        res[j] = val;
    }
    #pragma unroll
    for (int j = 0; j < 16; j += 4) {
        float4 o4 = make_float4(res[j], res[j + 1], res[j + 2], res[j + 3]);
        *(float4*)(orow + j) = o4;
    }
}

extern "C" void kernel_launch(void* const* d_in, const int* in_sizes, int n_in,
                              void* d_out, int out_size)
{
    const float* X = (const float*)d_in[0];      // (1024, 4096) fp32
    const float* w = (const float*)d_in[1];      // (15,) fp32
    // d_in[2] = B (15,4096,4096) — provably unused: W is fully determined by w
    // via the partition-structure decomposition above.
    float* out = (float*)d_out;                  // (1024, 4096) fp32
    (void)in_sizes; (void)n_in; (void)out_size;

    sym_equiv_kernel<<<1024, THREADS>>>(X, w, out);
}

// round 2
// speedup vs baseline: 1.7769x; 1.7769x over previous
#include <cuda_runtime.h>
#include <cuda_bf16.h>

#define NN 64
#define PAD 65          // bank-spread pad: bank(i2*PAD+i1) = (i1+i2)%32
#define ROWLEN 4096     // 64*64
#define THREADS 256

__global__ __launch_bounds__(THREADS)
void sym_equiv_kernel(const float* __restrict__ X,
                      const float* __restrict__ w,
                      float* __restrict__ out)
{
    __shared__ float Xs[NN * PAD];       // 16,640 B
    __shared__ float R1[NN];
    __shared__ float R2p[4][NN];         // column partial sums (4 row-quarters)
    __shared__ float Avec[NN], Cvec[NN], Evec[NN];
    __shared__ float Tp[2], Dp[2];
    __shared__ float ws[16];

    const int t = threadIdx.x;
    const int b = blockIdx.x;
    const float* __restrict__ xrow = X + (size_t)b * ROWLEN;

    if (t < 15) ws[t] = w[t];

    // ---- Phase 1: coalesced float4 row load -> regs + padded smem,
    //      plus row-sum partials (R1) via quad shuffles.
    const int i1 = t >> 2;               // row this thread owns
    const int ib = (t & 3) << 4;         // 16-col chunk start
    const float* g = xrow + i1 * NN + ib;
    float4 v0 = *(const float4*)(g + 0);
    float4 v1 = *(const float4*)(g + 4);
    float4 v2 = *(const float4*)(g + 8);
    float4 v3 = *(const float4*)(g + 12);

    float* srow = Xs + i1 * PAD + ib;
    srow[0]  = v0.x; srow[1]  = v0.y; srow[2]  = v0.z; srow[3]  = v0.w;
    srow[4]  = v1.x; srow[5]  = v1.y; srow[6]  = v1.z; srow[7]  = v1.w;
    srow[8]  = v2.x; srow[9]  = v2.y; srow[10] = v2.z; srow[11] = v2.w;
    srow[12] = v3.x; srow[13] = v3.y; srow[14] = v3.z; srow[15] = v3.w;

    float part = (v0.x + v0.y + v0.z + v0.w)
               + (v1.x + v1.y + v1.z + v1.w)
               + (v2.x + v2.y + v2.z + v2.w)
               + (v3.x + v3.y + v3.z + v3.w);
    part += __shfl_down_sync(0xffffffffu, part, 2, 4);
    part += __shfl_down_sync(0xffffffffu, part, 1, 4);
    if ((t & 3) == 0) R1[i1] = part;

    __syncthreads();                     // (1) Xs + R1 ready

    // ---- Phase 2a: column partial sums with ALL 256 threads.
    // thread t sums 16 rows of column (t&63); conflict-free (consecutive c).
    {
        const int c = t & 63;
        const int q = t >> 6;
        const float* p = Xs + (q * 16) * PAD + c;
        float s = 0.f;
        #pragma unroll
        for (int r = 0; r < 16; ++r) s += p[r * PAD];
        R2p[q][c] = s;
    }
    __syncthreads();                     // (2) R2p ready

    // ---- Phase 2b: fold R2, reduce T (sum R1) and D (trace) in 2 warps.
    float r1v = 0.f, r2v = 0.f, xdv = 0.f;
    if (t < 64) {
        r2v = R2p[0][t] + R2p[1][t] + R2p[2][t] + R2p[3][t];
        r1v = R1[t];
        xdv = Xs[t * (PAD + 1)];
        float a = r1v, d = xdv;
        #pragma unroll
        for (int o = 16; o > 0; o >>= 1) {
            a += __shfl_xor_sync(0xffffffffu, a, o);
            d += __shfl_xor_sync(0xffffffffu, d, o);
        }
        if ((t & 31) == 0) { Tp[t >> 5] = a; Dp[t >> 5] = d; }
    }
    __syncthreads();                     // (3) Tp/Dp ready

    // ---- Phase 3: fold weights into per-index vectors (map from
    // _set_partitions([0,1,2,3]) enumeration order; see R0 derivation).
    if (t < 64) {
        const float T = Tp[0] + Tp[1];
        const float D = Dp[0] + Dp[1];
        Avec[t] = ws[12] * r1v + ws[13] * r2v + ws[3] * xdv
                + ws[14] * T + ws[4] * D;                         // i1 terms + base
        Cvec[t] = ws[7]  * r1v + ws[10] * r2v + ws[1] * xdv;      // i2 terms
        Evec[t] = ws[5]  * r1v + ws[9]  * r2v + ws[0] * xdv
                + ws[11] * T + ws[2] * D;                         // diagonal terms
    }
    __syncthreads();                     // (4) vectors ready

    // ---- Phase 4: 16 outputs per thread. Direct term comes from the
    // REGISTERS loaded in Phase 1 (same thread owns X[i1, ib..ib+15]).
    const float w8v = ws[8], w6v = ws[6];
    const float K0  = Avec[i1];
    const float ev  = Evec[i1];
    float* orow = out + (size_t)b * ROWLEN + i1 * NN + ib;
    const float4* c4p = (const float4*)(Cvec + ib);
    const float4 xv[4] = {v0, v1, v2, v3};

    #pragma unroll
    for (int jj = 0; jj < 4; ++jj) {
        const float4 c4 = c4p[jj];
        const int i2b = ib + jj * 4;
        float4 o;
        o.x = K0 + c4.x + w8v * xv[jj].x + w6v * Xs[(i2b + 0) * PAD + i1];
        o.y = K0 + c4.y + w8v * xv[jj].y + w6v * Xs[(i2b + 1) * PAD + i1];
        o.z = K0 + c4.z + w8v * xv[jj].z + w6v * Xs[(i2b + 2) * PAD + i1];
        o.w = K0 + c4.w + w8v * xv[jj].w + w6v * Xs[(i2b + 3) * PAD + i1];
        const int dd = i1 - i2b;
        if (dd >= 0 && dd < 4) (&o.x)[dd] += ev;   // diagonal correction
        *(float4*)(orow + jj * 4) = o;
    }
}

extern "C" void kernel_launch(void* const* d_in, const int* in_sizes, int n_in,
                              void* d_out, int out_size)
{
    const float* X = (const float*)d_in[0];      // (1024, 4096) fp32
    const float* w = (const float*)d_in[1];      // (15,) fp32
    // d_in[2] = B (15,4096,4096) — provably unused: W is fully determined by w
    // via the partition-structure decomposition.
    float* out = (float*)d_out;                  // (1024, 4096) fp32
    (void)in_sizes; (void)n_in; (void)out_size;

    sym_equiv_kernel<<<1024, THREADS>>>(X, w, out);
}